// round 16
// baseline (speedup 1.0000x reference)
#include <cuda_runtime.h>
#include <cuda_fp16.h>

// ---------------------------------------------------------------------------
// Fused MoE via grouped fp16 mma.sync (m16n8k16) GEMMs, fp32 accumulate.
//   T=1024, H=2048, F=1408, E=32, K=6.
// init(zero out + x->fp16) -> prep -> GEMM1 (gate+up, fused SwiGLU -> Hh)
//          -> GEMM2 (fused weighted atomic scatter -> out)
// LDGSTS-issue-floor bound: A-side cp.async predicated off for padding rows
// (stale smem only feeds discarded output rows).
// ---------------------------------------------------------------------------

#define T_TOK 1024
#define HID   2048
#define FF    1408
#define NEXP  32
#define TOPK  6
#define NA    (T_TOK * TOPK)    // 6144
#define GUN   (2 * FF)          // 2816

typedef unsigned int u32;

// smem: 4 stages: A 256 rows x 80B (fp16) = 20KB; B 128 rows x 160B (fp32)
// = 20KB.  A at [0,81920), B at [81920,163840).
#define AST   20480u
#define BBASE 81920u
#define BST   20480u
#define SMB   163840
#define XSTR  68                // swiglu exchange stride (floats)

// ---------------- device scratch -------------------------------------------
__device__ int    d_count[NEXP];
__device__ int    d_off[NEXP];
__device__ int    d_tok[NA];
__device__ float  d_wts[NA];
__device__ __half d_xh[(size_t)T_TOK * HID];   // x in fp16
__device__ __half d_Hh[(size_t)NA * FF];       // swiglu output in fp16

// ---------------- PTX helpers ----------------------------------------------
__device__ __forceinline__ u32 smem_u32(const void* p) {
    u32 a;
    asm("{ .reg .u64 t; cvta.to.shared.u64 t, %1; cvt.u32.u64 %0, t; }"
        : "=r"(a) : "l"(p));
    return a;
}
__device__ __forceinline__ u32 pack2h(float2 v) {   // {lo=v.x, hi=v.y} fp16x2
    u32 r;
    asm("cvt.rn.f16x2.f32 %0, %1, %2;" : "=r"(r) : "f"(v.y), "f"(v.x));
    return r;
}
#define CP16(dst, src) \
    asm volatile("cp.async.cg.shared.global [%0], [%1], 16;" \
                 :: "r"(dst), "l"(src))
#define CP_COMMIT() asm volatile("cp.async.commit_group;" ::: "memory")
#define CP_WAIT(n)  asm volatile("cp.async.wait_group %0;" :: "n"(n) : "memory")
#define LDSM4(r0, r1, r2, r3, a) \
    asm volatile("ldmatrix.sync.aligned.m8n8.x4.shared.b16 {%0,%1,%2,%3}, [%4];" \
                 : "=r"(r0), "=r"(r1), "=r"(r2), "=r"(r3) : "r"(a))

__device__ __forceinline__ void mma16(float* d, u32 a0, u32 a1, u32 a2, u32 a3,
                                      u32 b0, u32 b1) {
    asm volatile(
        "mma.sync.aligned.m16n8k16.row.col.f32.f16.f16.f32 "
        "{%0,%1,%2,%3}, {%4,%5,%6,%7}, {%8,%9}, {%0,%1,%2,%3};"
        : "+f"(d[0]), "+f"(d[1]), "+f"(d[2]), "+f"(d[3])
        : "r"(a0), "r"(a1), "r"(a2), "r"(a3), "r"(b0), "r"(b1));
}

// ---------------- init (zero out + x->fp16) + prep --------------------------
__global__ void k_init(const float2* __restrict__ x, float2* __restrict__ out) {
    int i = blockIdx.x * blockDim.x + threadIdx.x;   // 1M threads
    out[i] = make_float2(0.f, 0.f);
    float2 v = x[i];
    ((__half2*)d_xh)[i] = __floats2half2_rn(v.x, v.y);
}
__global__ __launch_bounds__(256) void k_prep(const int* __restrict__ ids32,
                                              const float* __restrict__ tw) {
    __shared__ int f;
    __shared__ int scnt[NEXP];
    __shared__ int sfill[NEXP];
    const int tid = threadIdx.x;
    if (tid < NEXP) scnt[tid] = 0;
    if (tid == 0) f = 0;
    __syncthreads();
    int local = 0;
    for (int i = tid; i < NA / 2; i += 256)
        if (ids32[2 * i + 1] != 0) local = 1;
    if (local) f = 1;
    __syncthreads();
    const int flag = f;   // 1 => int32 ids
    for (int i = tid; i < NA; i += 256) {
        int e = flag ? ids32[i] : ids32[2 * i];
        atomicAdd(&scnt[e], 1);
    }
    __syncthreads();
    if (tid == 0) {
        int off = 0;
        for (int e = 0; e < NEXP; e++) {
            d_off[e] = off; sfill[e] = off;
            d_count[e] = scnt[e];
            off += scnt[e];
        }
    }
    __syncthreads();
    for (int i = tid; i < NA; i += 256) {
        int e = flag ? ids32[i] : ids32[2 * i];
        int pos = atomicAdd(&sfill[e], 1);
        d_tok[pos] = i / TOPK;
        d_wts[pos] = tw[i];
    }
}

// ---------------- grouped fp16 GEMM ----------------------------------------
// BM=256, BK=32, 512 threads (16 warps). Warp tile 64x32: four 16-row stripes
// at rows (wid&3)*16 + mt*64 (SMSP-interleaved), 32 cols at warpN=(wid>>2)*32.
// A staged fp16 (predicated: padding rows not staged) + ldmatrix fragments;
// B staged fp32 + cvt at fragment load.
// MODE 0: B tile = 64 gate rows + 64 up rows of same h-cols (n0=bx*64);
//   groups 0,1 gate / 2,3 up; up accs -> smem; gate applies silu*u -> d_Hh.
// MODE 1: BN=128 (n0=bx*128), weighted atomic scatter into Out.
template<int KDIM, int MODE>
__global__ __launch_bounds__(512, 1) void k_gemm(const float* __restrict__ Bw,
                                                 float* __restrict__ Out) {
    constexpr int NIT = KDIM / 32;
    extern __shared__ char smem[];
    const int e = blockIdx.y;
    const int cnt = d_count[e];
    if (cnt == 0) return;
    const int row0e = d_off[e];
    const int n0 = blockIdx.x * (MODE == 0 ? 64 : 128);
    const long long bStride = (MODE == 0) ? (long long)GUN * HID
                                          : (long long)HID * FF;
    const __half* A = (MODE == 0) ? d_xh : d_Hh;

    const int tid = threadIdx.x;
    const int wid = tid >> 5, lane = tid & 31;
    const int r4 = lane >> 2, c4 = lane & 3;
    const int s16   = (wid & 3) * 16;       // SMSP-interleaved M base
    const int group = wid >> 2;             // 0..3 N-group
    const int warpN = group * 32;
    const u32 sb = smem_u32(smem);

    // ldmatrix per-lane source offset within A tile (80B row stride)
    const int lq = lane & 7, quad = lane >> 3;
    const u32 ldsmOff = (u32)(((quad & 1) * 8 + lq) * 80 + (quad >> 1) * 16);

    // B loader: chunk = 16B slot (8 per 128B row), rb = 0..63, 2 rows/thread
    const int chunk = tid & 7, rb = tid >> 3;
    const float* bS[2];
    u32 bD[2];
#pragma unroll
    for (int p = 0; p < 2; p++) {
        int row = rb + 64 * p;
        long long gr = (MODE == 0)
            ? ((row < 64) ? (long long)(n0 + row) : (long long)(FF + n0 + row - 64))
            : (long long)(n0 + row);
        bS[p] = Bw + (long long)e * bStride + gr * KDIM + chunk * 4;
        bD[p] = sb + BBASE + (u32)row * 160u + (u32)chunk * 16u;
    }

    for (int m0 = 0; m0 < cnt; m0 += 256) {
        // A loader: 1024 16B-slots (4 per 64B fp16 row), 2 slots/thread.
        // Padding rows are NOT staged (no zero fill): their smem is stale,
        // which only affects D rows discarded by the rloc<cnt guards below.
        const __half* aS[2];
        int aV[2]; u32 aD[2];
#pragma unroll
        for (int j = 0; j < 2; j++) {
            int slot = tid + 512 * j;
            int r = slot >> 2, ch = slot & 3;
            int valid = (m0 + r) < cnt;
            long long src = 0;
            if (valid)
                src = (MODE == 0) ? (long long)d_tok[row0e + m0 + r]
                                  : (long long)(row0e + m0 + r);
            aS[j] = A + src * KDIM + ch * 8;
            aV[j] = valid;
            aD[j] = sb + (u32)r * 80u + (u32)ch * 16u;
        }
        const int rem = cnt - m0;
        const int tv = rem - s16;
        const int mtMax = (tv <= 0) ? 0 : ((tv + 63) >> 6 > 4 ? 4 : (tv + 63) >> 6);

        float acc[4][4][4];
#pragma unroll
        for (int mt = 0; mt < 4; mt++)
#pragma unroll
            for (int nt = 0; nt < 4; nt++)
#pragma unroll
                for (int q = 0; q < 4; q++) acc[mt][nt][q] = 0.f;

#define ISSUE(s, k0) do {                                                  \
        u32 _ao = (u32)(s) * AST;                                          \
        u32 _bo = (u32)(s) * BST;                                          \
        _Pragma("unroll")                                                  \
        for (int _j = 0; _j < 2; _j++)                                     \
            if (aV[_j]) CP16(aD[_j] + _ao, aS[_j] + (k0));                 \
        _Pragma("unroll")                                                  \
        for (int _p = 0; _p < 2; _p++)                                     \
            CP16(bD[_p] + _bo, bS[_p] + (k0));                             \
    } while (0)

        ISSUE(0, 0);  CP_COMMIT();
        ISSUE(1, 32); CP_COMMIT();
        ISSUE(2, 64); CP_COMMIT();

        for (int it = 0; it < NIT; it++) {
            const int buf = it & 3;
            CP_WAIT(2);
            __syncthreads();
            const int ns = it + 3;
            if (ns < NIT) ISSUE(ns & 3, ns * 32);
            CP_COMMIT();

            const u32 aBase = sb + buf * AST + ldsmOff;
            const float* Bf = (const float*)(smem + BBASE + buf * BST);
#pragma unroll
            for (int ks = 0; ks < 2; ks++) {
                u32 b[4][2];
#pragma unroll
                for (int nt = 0; nt < 4; nt++) {
                    int cb = (warpN + nt * 8 + r4) * 40 + ks * 16 + 2 * c4;
                    b[nt][0] = pack2h(*(const float2*)&Bf[cb]);
                    b[nt][1] = pack2h(*(const float2*)&Bf[cb + 8]);
                }
#pragma unroll
                for (int mt = 0; mt < 4; mt++) {
                    if (mt < mtMax) {
                        u32 a0, a1, a2, a3;
                        LDSM4(a0, a1, a2, a3,
                              aBase + (u32)(s16 + mt * 64) * 80u + (u32)ks * 32u);
#pragma unroll
                        for (int nt = 0; nt < 4; nt++)
                            mma16(acc[mt][nt], a0, a1, a2, a3,
                                  b[nt][0], b[nt][1]);
                    }
                }
            }
        }
        CP_WAIT(0);

        if (MODE == 0) {
            // ---- fused SwiGLU epilogue: up groups -> smem, gate groups read
            float* xs = (float*)smem;
            __syncthreads();                    // pipeline smem now dead
            if (group >= 2) {
                const int xc = (group - 2) * 32;
#pragma unroll
                for (int mt = 0; mt < 4; mt++) {
                    int r = s16 + mt * 64 + r4;
#pragma unroll
                    for (int nt = 0; nt < 4; nt++) {
                        int col = xc + nt * 8 + c4 * 2;
                        *(float2*)&xs[r * XSTR + col] =
                            make_float2(acc[mt][nt][0], acc[mt][nt][1]);
                        *(float2*)&xs[(r + 8) * XSTR + col] =
                            make_float2(acc[mt][nt][2], acc[mt][nt][3]);
                    }
                }
            }
            __syncthreads();
            if (group < 2) {
                const int xc = group * 32;
#pragma unroll
                for (int mt = 0; mt < 4; mt++) {
                    int r = s16 + mt * 64 + r4;
                    int rloc = m0 + r;
#pragma unroll
                    for (int nt = 0; nt < 4; nt++) {
                        int col = xc + nt * 8 + c4 * 2;
                        if (rloc < cnt) {
                            float2 u = *(const float2*)&xs[r * XSTR + col];
                            float g0 = acc[mt][nt][0], g1 = acc[mt][nt][1];
                            float h0 = g0 / (1.f + __expf(-g0)) * u.x;
                            float h1 = g1 / (1.f + __expf(-g1)) * u.y;
                            *(__half2*)&d_Hh[(long long)(row0e + rloc) * FF
                                + n0 + col] = __floats2half2_rn(h0, h1);
                        }
                        if (rloc + 8 < cnt) {
                            float2 u = *(const float2*)&xs[(r + 8) * XSTR + col];
                            float g0 = acc[mt][nt][2], g1 = acc[mt][nt][3];
                            float h0 = g0 / (1.f + __expf(-g0)) * u.x;
                            float h1 = g1 / (1.f + __expf(-g1)) * u.y;
                            *(__half2*)&d_Hh[(long long)(row0e + rloc + 8) * FF
                                + n0 + col] = __floats2half2_rn(h0, h1);
                        }
                    }
                }
            }
        } else {
            // ---- weighted atomic scatter into Out ----
#pragma unroll
            for (int mt = 0; mt < 4; mt++) {
                int rloc = m0 + s16 + mt * 64 + r4;
                int v0 = rloc < cnt, v1 = (rloc + 8) < cnt;
                int t0 = 0, t1 = 0; float w0 = 0.f, w1 = 0.f;
                if (v0) { t0 = d_tok[row0e + rloc];     w0 = d_wts[row0e + rloc]; }
                if (v1) { t1 = d_tok[row0e + rloc + 8]; w1 = d_wts[row0e + rloc + 8]; }
#pragma unroll
                for (int nt = 0; nt < 4; nt++) {
                    int col = n0 + warpN + nt * 8 + c4 * 2;
                    if (v0) {
                        float* o = Out + (long long)t0 * HID + col;
                        atomicAdd(o,     w0 * acc[mt][nt][0]);
                        atomicAdd(o + 1, w0 * acc[mt][nt][1]);
                    }
                    if (v1) {
                        float* o = Out + (long long)t1 * HID + col;
                        atomicAdd(o,     w1 * acc[mt][nt][2]);
                        atomicAdd(o + 1, w1 * acc[mt][nt][3]);
                    }
                }
            }
        }
        __syncthreads();
#undef ISSUE
    }
}

// ---------------- launch ----------------------------------------------------
extern "C" void kernel_launch(void* const* d_in, const int* in_sizes, int n_in,
                              void* d_out, int out_size) {
    const float* x   = (const float*)d_in[0];
    const float* w1  = (const float*)d_in[1];
    const float* w2  = (const float*)d_in[2];
    const float* tw  = (const float*)d_in[3];
    const int*   ids = (const int*)d_in[4];
    float* out = (float*)d_out;

    cudaFuncSetAttribute(k_gemm<HID, 0>,
                         cudaFuncAttributeMaxDynamicSharedMemorySize, SMB);
    cudaFuncSetAttribute(k_gemm<FF, 1>,
                         cudaFuncAttributeMaxDynamicSharedMemorySize, SMB);

    k_init<<<2048, 512>>>((const float2*)x, (float2*)out);
    k_prep<<<1, 256>>>(ids, tw);
    k_gemm<HID, 0><<<dim3(FF / 64, NEXP), 512, SMB>>>(w1, nullptr);
    k_gemm<FF, 1><<<dim3(HID / 128, NEXP), 512, SMB>>>(w2, out);
}

// round 17
// speedup vs baseline: 1.0529x; 1.0529x over previous
#include <cuda_runtime.h>
#include <cuda_fp16.h>

// ---------------------------------------------------------------------------
// Fused MoE via grouped fp16 mma.sync (m16n8k16) GEMMs, fp32 accumulate.
//   T=1024, H=2048, F=1408, E=32, K=6.
// Launch 1: init (zero out, x->fp16) + routing prep (one block).
// Launch 2: k_moe — GEMM1 CTAs (bids 0..703, gate+up + fused SwiGLU -> Hh
//   fp16) and GEMM2 CTAs (bids 704..1215, weighted atomic scatter -> out)
//   in ONE kernel; GEMM2 CTAs gate on per-expert done flags (GEMM1 bids all
//   precede GEMM2 bids, so in-order CTA placement makes this deadlock-free).
// GEMM core = R13: BM=256 (weights staged once), 4-stage cp.async, ldmatrix
// A fragments, SMSP-interleaved M-stripes.
// ---------------------------------------------------------------------------

#define T_TOK 1024
#define HID   2048
#define FF    1408
#define NEXP  32
#define TOPK  6
#define NA    (T_TOK * TOPK)    // 6144
#define GUN   (2 * FF)          // 2816
#define G1CTAS (NEXP * 22)      // 704
#define G2CTAS (NEXP * 16)      // 512

typedef unsigned int u32;

// smem: 4 stages: A 256 rows x 80B (fp16) = 20KB; B 128 rows x 160B (fp32)
// = 20KB.  A at [0,81920), B at [81920,163840).
#define AST   20480u
#define BBASE 81920u
#define BST   20480u
#define SMB   163840
#define XSTR  68                // swiglu exchange stride (floats)

// ---------------- device scratch -------------------------------------------
__device__ int    d_count[NEXP];
__device__ int    d_off[NEXP];
__device__ int    d_done[NEXP];
__device__ int    d_tok[NA];
__device__ float  d_wts[NA];
__device__ __half d_xh[(size_t)T_TOK * HID];   // x in fp16
__device__ __half d_Hh[(size_t)NA * FF];       // swiglu output in fp16

// ---------------- PTX helpers ----------------------------------------------
__device__ __forceinline__ u32 smem_u32(const void* p) {
    u32 a;
    asm("{ .reg .u64 t; cvta.to.shared.u64 t, %1; cvt.u32.u64 %0, t; }"
        : "=r"(a) : "l"(p));
    return a;
}
__device__ __forceinline__ u32 pack2h(float2 v) {   // {lo=v.x, hi=v.y} fp16x2
    u32 r;
    asm("cvt.rn.f16x2.f32 %0, %1, %2;" : "=r"(r) : "f"(v.y), "f"(v.x));
    return r;
}
#define CP16(dst, src, sz) \
    asm volatile("cp.async.cg.shared.global [%0], [%1], 16, %2;" \
                 :: "r"(dst), "l"(src), "r"(sz))
#define CP_COMMIT() asm volatile("cp.async.commit_group;" ::: "memory")
#define CP_WAIT(n)  asm volatile("cp.async.wait_group %0;" :: "n"(n) : "memory")
#define LDSM4(r0, r1, r2, r3, a) \
    asm volatile("ldmatrix.sync.aligned.m8n8.x4.shared.b16 {%0,%1,%2,%3}, [%4];" \
                 : "=r"(r0), "=r"(r1), "=r"(r2), "=r"(r3) : "r"(a))

__device__ __forceinline__ void mma16(float* d, u32 a0, u32 a1, u32 a2, u32 a3,
                                      u32 b0, u32 b1) {
    asm volatile(
        "mma.sync.aligned.m16n8k16.row.col.f32.f16.f16.f32 "
        "{%0,%1,%2,%3}, {%4,%5,%6,%7}, {%8,%9}, {%0,%1,%2,%3};"
        : "+f"(d[0]), "+f"(d[1]), "+f"(d[2]), "+f"(d[3])
        : "r"(a0), "r"(a1), "r"(a2), "r"(a3), "r"(b0), "r"(b1));
}

// ---------------- init (zero out + x->fp16) + prep, one launch --------------
__global__ __launch_bounds__(512) void k_init_prep(const float2* __restrict__ x,
                                                   float2* __restrict__ out,
                                                   const int* __restrict__ ids32,
                                                   const float* __restrict__ tw) {
    const int b = blockIdx.x;
    if (b < 2048) {                          // init slice
        int i = b * 512 + threadIdx.x;       // 1M float2
        out[i] = make_float2(0.f, 0.f);
        float2 v = x[i];
        ((__half2*)d_xh)[i] = __floats2half2_rn(v.x, v.y);
        return;
    }
    // ---- routing prep (single block) ----
    __shared__ int f;
    __shared__ int scnt[NEXP];
    __shared__ int sfill[NEXP];
    const int tid = threadIdx.x;
    if (tid < NEXP) { scnt[tid] = 0; d_done[tid] = 0; }
    if (tid == 0) f = 0;
    __syncthreads();
    int local = 0;
    for (int i = tid; i < NA / 2; i += 512)
        if (ids32[2 * i + 1] != 0) local = 1;
    if (local) f = 1;
    __syncthreads();
    const int flag = f;   // 1 => int32 ids
    for (int i = tid; i < NA; i += 512) {
        int e = flag ? ids32[i] : ids32[2 * i];
        atomicAdd(&scnt[e], 1);
    }
    __syncthreads();
    if (tid == 0) {
        int off = 0;
        for (int e = 0; e < NEXP; e++) {
            d_off[e] = off; sfill[e] = off;
            d_count[e] = scnt[e];
            off += scnt[e];
        }
    }
    __syncthreads();
    for (int i = tid; i < NA; i += 512) {
        int e = flag ? ids32[i] : ids32[2 * i];
        int pos = atomicAdd(&sfill[e], 1);
        d_tok[pos] = i / TOPK;
        d_wts[pos] = tw[i];
    }
}

// ---------------- grouped fp16 GEMM body (R13 core) -------------------------
// BM=256, BK=32, 512 threads (16 warps). Warp tile 64x32: four 16-row stripes
// at rows (wid&3)*16 + mt*64 (SMSP-interleaved), 32 cols at warpN=(wid>>2)*32.
// A staged fp16 + ldmatrix.x4 fragments; B staged fp32 + cvt at load.
// MODE 0: B tile = 64 gate rows + 64 up rows of same h-cols (n0=bx*64);
//   groups 0,1 gate / 2,3 up; up accs -> smem; gate applies silu*u -> d_Hh.
// MODE 1: BN=128 (n0=bx*128), weighted atomic scatter into Out.
template<int KDIM, int MODE>
__device__ __forceinline__ void gemm_body(char* smem, int e, int bx,
                                          const float* __restrict__ Bw,
                                          float* __restrict__ Out) {
    constexpr int NIT = KDIM / 32;
    const int cnt = d_count[e];
    const int row0e = d_off[e];
    const int n0 = bx * (MODE == 0 ? 64 : 128);
    const long long bStride = (MODE == 0) ? (long long)GUN * HID
                                          : (long long)HID * FF;
    const __half* A = (MODE == 0) ? d_xh : d_Hh;

    const int tid = threadIdx.x;
    const int wid = tid >> 5, lane = tid & 31;
    const int r4 = lane >> 2, c4 = lane & 3;
    const int s16   = (wid & 3) * 16;       // SMSP-interleaved M base
    const int group = wid >> 2;             // 0..3 N-group
    const int warpN = group * 32;
    const u32 sb = smem_u32(smem);

    // ldmatrix per-lane source offset within A tile (80B row stride)
    const int lq = lane & 7, quad = lane >> 3;
    const u32 ldsmOff = (u32)(((quad & 1) * 8 + lq) * 80 + (quad >> 1) * 16);

    // B loader: chunk = 16B slot (8 per 128B row), rb = 0..63, 2 rows/thread
    const int chunk = tid & 7, rb = tid >> 3;
    const float* bS[2];
    u32 bD[2];
#pragma unroll
    for (int p = 0; p < 2; p++) {
        int row = rb + 64 * p;
        long long gr = (MODE == 0)
            ? ((row < 64) ? (long long)(n0 + row) : (long long)(FF + n0 + row - 64))
            : (long long)(n0 + row);
        bS[p] = Bw + (long long)e * bStride + gr * KDIM + chunk * 4;
        bD[p] = sb + BBASE + (u32)row * 160u + (u32)chunk * 16u;
    }

    for (int m0 = 0; m0 < cnt; m0 += 256) {
        // A loader: 1024 16B-slots (4 per 64B fp16 row), 2 slots/thread
        const __half* aS[2];
        u32 aV[2], aD[2];
#pragma unroll
        for (int j = 0; j < 2; j++) {
            int slot = tid + 512 * j;
            int r = slot >> 2, ch = slot & 3;
            int valid = (m0 + r) < cnt;
            long long src = 0;
            if (valid)
                src = (MODE == 0) ? (long long)d_tok[row0e + m0 + r]
                                  : (long long)(row0e + m0 + r);
            aS[j] = A + src * KDIM + ch * 8;
            aV[j] = valid ? 16u : 0u;
            aD[j] = sb + (u32)r * 80u + (u32)ch * 16u;
        }
        const int rem = cnt - m0;
        const int tv = rem - s16;
        const int mtMax = (tv <= 0) ? 0 : ((tv + 63) >> 6 > 4 ? 4 : (tv + 63) >> 6);

        float acc[4][4][4];
#pragma unroll
        for (int mt = 0; mt < 4; mt++)
#pragma unroll
            for (int nt = 0; nt < 4; nt++)
#pragma unroll
                for (int q = 0; q < 4; q++) acc[mt][nt][q] = 0.f;

#define ISSUE(s, k0) do {                                                  \
        u32 _ao = (u32)(s) * AST;                                          \
        u32 _bo = (u32)(s) * BST;                                          \
        _Pragma("unroll")                                                  \
        for (int _j = 0; _j < 2; _j++)                                     \
            CP16(aD[_j] + _ao, aS[_j] + (k0), aV[_j]);                     \
        _Pragma("unroll")                                                  \
        for (int _p = 0; _p < 2; _p++)                                     \
            CP16(bD[_p] + _bo, bS[_p] + (k0), 16u);                        \
    } while (0)

        ISSUE(0, 0);  CP_COMMIT();
        ISSUE(1, 32); CP_COMMIT();
        ISSUE(2, 64); CP_COMMIT();

        for (int it = 0; it < NIT; it++) {
            const int buf = it & 3;
            CP_WAIT(2);
            __syncthreads();
            const int ns = it + 3;
            if (ns < NIT) ISSUE(ns & 3, ns * 32);
            CP_COMMIT();

            const u32 aBase = sb + buf * AST + ldsmOff;
            const float* Bf = (const float*)(smem + BBASE + buf * BST);
#pragma unroll
            for (int ks = 0; ks < 2; ks++) {
                u32 b[4][2];
#pragma unroll
                for (int nt = 0; nt < 4; nt++) {
                    int cb = (warpN + nt * 8 + r4) * 40 + ks * 16 + 2 * c4;
                    b[nt][0] = pack2h(*(const float2*)&Bf[cb]);
                    b[nt][1] = pack2h(*(const float2*)&Bf[cb + 8]);
                }
#pragma unroll
                for (int mt = 0; mt < 4; mt++) {
                    if (mt < mtMax) {
                        u32 a0, a1, a2, a3;
                        LDSM4(a0, a1, a2, a3,
                              aBase + (u32)(s16 + mt * 64) * 80u + (u32)ks * 32u);
#pragma unroll
                        for (int nt = 0; nt < 4; nt++)
                            mma16(acc[mt][nt], a0, a1, a2, a3,
                                  b[nt][0], b[nt][1]);
                    }
                }
            }
        }
        CP_WAIT(0);

        if (MODE == 0) {
            // ---- fused SwiGLU epilogue: up groups -> smem, gate groups read
            float* xs = (float*)smem;
            __syncthreads();                    // pipeline smem now dead
            if (group >= 2) {
                const int xc = (group - 2) * 32;
#pragma unroll
                for (int mt = 0; mt < 4; mt++) {
                    int r = s16 + mt * 64 + r4;
#pragma unroll
                    for (int nt = 0; nt < 4; nt++) {
                        int col = xc + nt * 8 + c4 * 2;
                        *(float2*)&xs[r * XSTR + col] =
                            make_float2(acc[mt][nt][0], acc[mt][nt][1]);
                        *(float2*)&xs[(r + 8) * XSTR + col] =
                            make_float2(acc[mt][nt][2], acc[mt][nt][3]);
                    }
                }
            }
            __syncthreads();
            if (group < 2) {
                const int xc = group * 32;
#pragma unroll
                for (int mt = 0; mt < 4; mt++) {
                    int r = s16 + mt * 64 + r4;
                    int rloc = m0 + r;
#pragma unroll
                    for (int nt = 0; nt < 4; nt++) {
                        int col = xc + nt * 8 + c4 * 2;
                        if (rloc < cnt) {
                            float2 u = *(const float2*)&xs[r * XSTR + col];
                            float g0 = acc[mt][nt][0], g1 = acc[mt][nt][1];
                            float h0 = g0 / (1.f + __expf(-g0)) * u.x;
                            float h1 = g1 / (1.f + __expf(-g1)) * u.y;
                            *(__half2*)&d_Hh[(long long)(row0e + rloc) * FF
                                + n0 + col] = __floats2half2_rn(h0, h1);
                        }
                        if (rloc + 8 < cnt) {
                            float2 u = *(const float2*)&xs[(r + 8) * XSTR + col];
                            float g0 = acc[mt][nt][2], g1 = acc[mt][nt][3];
                            float h0 = g0 / (1.f + __expf(-g0)) * u.x;
                            float h1 = g1 / (1.f + __expf(-g1)) * u.y;
                            *(__half2*)&d_Hh[(long long)(row0e + rloc + 8) * FF
                                + n0 + col] = __floats2half2_rn(h0, h1);
                        }
                    }
                }
            }
        } else {
            // ---- weighted atomic scatter into Out ----
#pragma unroll
            for (int mt = 0; mt < 4; mt++) {
                int rloc = m0 + s16 + mt * 64 + r4;
                int v0 = rloc < cnt, v1 = (rloc + 8) < cnt;
                int t0 = 0, t1 = 0; float w0 = 0.f, w1 = 0.f;
                if (v0) { t0 = d_tok[row0e + rloc];     w0 = d_wts[row0e + rloc]; }
                if (v1) { t1 = d_tok[row0e + rloc + 8]; w1 = d_wts[row0e + rloc + 8]; }
#pragma unroll
                for (int nt = 0; nt < 4; nt++) {
                    int col = n0 + warpN + nt * 8 + c4 * 2;
                    if (v0) {
                        float* o = Out + (long long)t0 * HID + col;
                        atomicAdd(o,     w0 * acc[mt][nt][0]);
                        atomicAdd(o + 1, w0 * acc[mt][nt][1]);
                    }
                    if (v1) {
                        float* o = Out + (long long)t1 * HID + col;
                        atomicAdd(o,     w1 * acc[mt][nt][2]);
                        atomicAdd(o + 1, w1 * acc[mt][nt][3]);
                    }
                }
            }
        }
        __syncthreads();
#undef ISSUE
    }
}

// ---------------- fused MoE kernel ------------------------------------------
// bids [0, 704): GEMM1 tiles (e = bid/22, bx = bid%22); on completion bump
// d_done[e].  bids [704, 1216): GEMM2 tiles (e = t/16, bx = t%16); spin until
// d_done[e] == 22.  GEMM1 bids all precede GEMM2 bids, and CTA slots are
// filled in ascending bid order, so spinners can never starve producers.
__global__ __launch_bounds__(512, 1) void k_moe(const float* __restrict__ w1,
                                                const float* __restrict__ w2,
                                                float* __restrict__ out) {
    extern __shared__ char smem[];
    const int bid = blockIdx.x;
    if (bid < G1CTAS) {
        const int e = bid / 22, bx = bid % 22;
        if (d_count[e] > 0) gemm_body<HID, 0>(smem, e, bx, w1, nullptr);
        if (threadIdx.x == 0) {
            __threadfence();
            atomicAdd(&d_done[e], 1);
        }
    } else {
        const int t = bid - G1CTAS;
        const int e = t / 16, bx = t % 16;
        if (d_count[e] == 0) return;
        if (threadIdx.x == 0) {
            while (atomicAdd(&d_done[e], 0) < 22) __nanosleep(200);
            __threadfence();
        }
        __syncthreads();
        gemm_body<FF, 1>(smem, e, bx, w2, out);
    }
}

// ---------------- launch ----------------------------------------------------
extern "C" void kernel_launch(void* const* d_in, const int* in_sizes, int n_in,
                              void* d_out, int out_size) {
    const float* x   = (const float*)d_in[0];
    const float* w1  = (const float*)d_in[1];
    const float* w2  = (const float*)d_in[2];
    const float* tw  = (const float*)d_in[3];
    const int*   ids = (const int*)d_in[4];
    float* out = (float*)d_out;

    cudaFuncSetAttribute(k_moe,
                         cudaFuncAttributeMaxDynamicSharedMemorySize, SMB);

    k_init_prep<<<2049, 512>>>((const float2*)x, (float2*)out, ids, tw);
    k_moe<<<G1CTAS + G2CTAS, 512, SMB>>>(w1, w2, out);
}